// round 12
// baseline (speedup 1.0000x reference)
#include <cuda_runtime.h>

#define BATCH   4096
#define IN_W    1024
#define DEPTH   8
#define BLOCKS  64
#define NACT    8
#define GROW    512
#define TOTAL   5120
#define OUT_W   512
#define THREADS 64          // threads per CTA (one butterfly block)
#define CPT     4           // batch cols per thread (two f32x2 lanes)

// 84 MB scratch state (static __device__ global: allowed, no runtime alloc)
__device__ float g_data[(size_t)TOTAL * BATCH];

typedef unsigned long long ull;

// Liveness masks: alive_sc[m][i] = row idx[m][i] is read by a later module;
// alive_act[m][u] = act row IN_W+512m+u is read by a later module. (m = 0..6)
__device__ unsigned char g_alive_sc[DEPTH - 1][1024];
__device__ unsigned char g_alive_act[DEPTH - 1][512];

__device__ __forceinline__ ull pk2(float x, float y) {
    ull r; asm("mov.b64 %0, {%1, %2};" : "=l"(r) : "f"(x), "f"(y)); return r;
}
__device__ __forceinline__ void upk2(ull v, float& x, float& y) {
    asm("mov.b64 {%0, %1}, %2;" : "=f"(x), "=f"(y) : "l"(v));
}
// Packed f32x2 FMA/MUL — Blackwell FFMA2 path (PTX-only)
__device__ __forceinline__ ull fma2(ull a, ull b, ull c) {
    ull d; asm("fma.rn.f32x2 %0, %1, %2, %3;" : "=l"(d) : "l"(a), "l"(b), "l"(c)); return d;
}
__device__ __forceinline__ ull mul2(ull a, ull b) {
    ull d; asm("mul.rn.f32x2 %0, %1, %2;" : "=l"(d) : "l"(a), "l"(b)); return d;
}
__device__ __forceinline__ float sqrt_ap(float x) {
    float r; asm("sqrt.approx.f32 %0, %1;" : "=f"(r) : "f"(x)); return r;
}
__device__ __forceinline__ float actf(float p) {
    return 0.5f * (p + sqrt_ap(fmaf(p, p, 1.0f)));
}
__device__ __forceinline__ ull mk_keep() {     // evict_last: row re-read later
    ull pol;
    asm("createpolicy.fractional.L2::evict_last.b64 %0, 1.0;" : "=l"(pol));
    return pol;
}
__device__ __forceinline__ ull mk_stream() {   // evict_first: last use
    ull pol;
    asm("createpolicy.fractional.L2::evict_first.b64 %0, 1.0;" : "=l"(pol));
    return pol;
}
// 128-bit state accesses with cache policy
__device__ __forceinline__ ulonglong2 ldg_pol2(const float* p, ull pol) {
    ulonglong2 v;
    asm("ld.global.L2::cache_hint.v2.u64 {%0, %1}, [%2], %3;"
        : "=l"(v.x), "=l"(v.y) : "l"(p), "l"(pol));
    return v;
}
__device__ __forceinline__ void stg_pol2(float* p, ull x, ull y, ull pol) {
    asm volatile("st.global.L2::cache_hint.v2.u64 [%0], {%1, %2}, %3;"
                 :: "l"(p), "l"(x), "l"(y), "l"(pol));
}
__device__ __forceinline__ void stg_cs2(float* p, ull x, ull y) {
    asm volatile("st.global.cs.v2.u64 [%0], {%1, %2};"
                 :: "l"(p), "l"(x), "l"(y));
}

// ---------------------------------------------------------------------------
// One-time: liveness masks via reverse sweep over indices.
// mark[r]=1 iff row r is read by a module > m.
// ---------------------------------------------------------------------------
__global__ void alive_kernel(const int* __restrict__ indices) {
    __shared__ unsigned char mark[TOTAL];
    const int t = threadIdx.x;
    #pragma unroll
    for (int i = t; i < TOTAL; i += 1024) mark[i] = 0;
    __syncthreads();
    mark[indices[7 * 1024 + t]] = 1;          // reads of the last module
    __syncthreads();
    for (int m = DEPTH - 2; m >= 0; m--) {
        g_alive_sc[m][t] = mark[indices[m * 1024 + t]];
        if (t < 512) g_alive_act[m][t] = mark[IN_W + GROW * m + t];
        __syncthreads();
        if (m > 0) {
            mark[indices[m * 1024 + t]] = 1;
            __syncthreads();
        }
    }
}

// ---------------------------------------------------------------------------
// One butterfly module. CTA = 64 threads = one butterfly blk x 256 batch cols;
// thread owns 4 cols of all 16 rows as two f32x2 lanes -> all accesses 128-bit.
// occ-7, 1024 CTAs -> one wave. PDL prologue computes trig via sincosf
// (overlapped with previous module's tail); g_data touched only after
// griddepsync. MODE: 0 = middle, 1 = first (input*scales), 2 = last (-> d_out)
// ---------------------------------------------------------------------------
template<int MODE>
__global__ __launch_bounds__(THREADS, 7)
void module_kernel(const float* __restrict__ biases,  // [512]    this module
                   const int*   __restrict__ idx,     // [1024]   this module
                   const float* __restrict__ angles,  // [8][512] this module
                   int mod,
                   const float* __restrict__ input,   // (1024,4096) for FIRST
                   const float* __restrict__ scales,  // (1024,)     for FIRST
                   float* __restrict__ out_ext)       // d_out for LAST
{
    const int blk = blockIdx.y;
    const int tid = threadIdx.x;

    __shared__ int   s_idx[16];
    __shared__ ull   s_scl[16];
    __shared__ float s_bias[NACT];
    __shared__ unsigned char s_alsc[16];
    __shared__ unsigned char s_alact[NACT];
    __shared__ __align__(16) ulonglong2 s_cs[64];

    // ---- PDL prologue: tables + trig only, no g_data ----
    {
        int L = tid >> 3, a = tid & 7;
        float sn, cs;
        sincosf(angles[L * 512 + blk * 8 + a], &sn, &cs);
        s_cs[tid] = make_ulonglong2(pk2(cs, cs), pk2(sn, sn));
    }
    if (tid < 16) {
        int row = idx[blk * 16 + tid];
        s_idx[tid]  = row;
        s_alsc[tid] = (MODE == 2) ? 0 : g_alive_sc[mod][blk * 16 + tid];
        if (MODE == 1) { float s = scales[row]; s_scl[tid] = pk2(s, s); }
    }
    if (tid < 8) {
        s_bias[tid]  = biases[blk * 8 + tid];
        s_alact[tid] = (MODE == 2) ? 1 : g_alive_act[mod][blk * NACT + tid];
    }
    __syncthreads();

    const int b = (blockIdx.x * THREADS + tid) * CPT;  // first of 4 cols
    const ull SGN = 0x8000000080000000ULL;
    const ull pk  = mk_keep();
    const ull ps  = mk_stream();

    // ---- wait for previous module's stores ----
    if (MODE != 1) cudaGridDependencySynchronize();

    // Gather 16 rows (16 independent LDG.128 -> MLP=16)
    ull vx[16], vy[16];
    #pragma unroll
    for (int j = 0; j < 16; j++) {
        if (MODE == 1) {
            ulonglong2 u = *(const ulonglong2*)(input + (size_t)s_idx[j] * BATCH + b);
            vx[j] = u.x; vy[j] = u.y;
        } else {
            ulonglong2 u = ldg_pol2(g_data + (size_t)s_idx[j] * BATCH + b,
                                    s_alsc[j] ? pk : ps);
            vx[j] = u.x; vy[j] = u.y;
        }
    }
    if (MODE == 1) {
        #pragma unroll
        for (int j = 0; j < 16; j++) {
            vx[j] = mul2(vx[j], s_scl[j]);
            vy[j] = mul2(vy[j], s_scl[j]);
        }
    }

    // 4 IN rotation layers (strides 1,2,4,8), all in registers
    #pragma unroll
    for (int k = 0; k < 4; k++) {
        const int st = 1 << k;
        #pragma unroll
        for (int g = 0; g < 16; g += 2 * st) {
            #pragma unroll
            for (int j = 0; j < st; j++) {
                const int lo = g + j, hi = lo + st;
                const ulonglong2 cs = s_cs[k * 8 + (g >> 1) + j];  // LDS.128
                const ull ns = cs.y ^ SGN;                         // -s on ALU
                ull xl, xh;
                xl = vx[lo]; xh = vx[hi];
                vx[lo] = fma2(cs.x, xl, mul2(cs.y, xh));
                vx[hi] = fma2(ns,   xl, mul2(cs.x, xh));
                xl = vy[lo]; xh = vy[hi];
                vy[lo] = fma2(cs.x, xl, mul2(cs.y, xh));
                vy[hi] = fma2(ns,   xl, mul2(cs.x, xh));
            }
        }
    }

    // Activation on rows 0..7; write live act rows (d_out for last module)
    #pragma unroll
    for (int u = 0; u < NACT; u++) {
        const float bb = s_bias[u];
        float x0, x1, x2, x3;
        upk2(vx[u], x0, x1);
        upk2(vy[u], x2, x3);
        x0 = actf(x0 + bb); x1 = actf(x1 + bb);
        x2 = actf(x2 + bb); x3 = actf(x3 + bb);
        vx[u] = pk2(x0, x1);
        vy[u] = pk2(x2, x3);
        if (MODE == 2)
            stg_cs2(out_ext + (size_t)(blk * NACT + u) * BATCH + b, vx[u], vy[u]);
        else if (s_alact[u])
            stg_pol2(g_data + (size_t)(IN_W + GROW * mod + blk * NACT + u) * BATCH + b,
                     vx[u], vy[u], pk);
    }

    if (MODE != 2) {
        // 4 OUT rotation layers (trig layers 4..7, strides 1,2,4,8)
        #pragma unroll
        for (int k = 0; k < 4; k++) {
            const int st = 1 << k;
            #pragma unroll
            for (int g = 0; g < 16; g += 2 * st) {
                #pragma unroll
                for (int j = 0; j < st; j++) {
                    const int lo = g + j, hi = lo + st;
                    const ulonglong2 cs = s_cs[(4 + k) * 8 + (g >> 1) + j];
                    const ull ns = cs.y ^ SGN;
                    ull xl, xh;
                    xl = vx[lo]; xh = vx[hi];
                    vx[lo] = fma2(cs.x, xl, mul2(cs.y, xh));
                    vx[hi] = fma2(ns,   xl, mul2(cs.x, xh));
                    xl = vy[lo]; xh = vy[hi];
                    vy[lo] = fma2(cs.x, xl, mul2(cs.y, xh));
                    vy[hi] = fma2(ns,   xl, mul2(cs.x, xh));
                }
            }
        }
        // Scatter back only live rows (warp-uniform predicate, STG.128)
        #pragma unroll
        for (int j = 0; j < 16; j++)
            if (s_alsc[j])
                stg_pol2(g_data + (size_t)s_idx[j] * BATCH + b, vx[j], vy[j], pk);
    }

    // Let the next PDL kernel in as soon as our work is done.
    cudaTriggerProgrammaticLaunchCompletion();
}

// ---------------------------------------------------------------------------
extern "C" void kernel_launch(void* const* d_in, const int* in_sizes, int n_in,
                              void* d_out, int out_size) {
    const float* input   = (const float*)d_in[0];   // (1024, 4096)
    const float* scales  = (const float*)d_in[1];   // (1024,)
    const float* angles  = (const float*)d_in[2];   // (8, 8, 512)
    const float* biases  = (const float*)d_in[3];   // (8, 512)
    const int*   indices = (const int*)d_in[4];     // (8, 1024)
    float* out = (float*)d_out;                     // (512, 4096)

    alive_kernel<<<1, 1024>>>(indices);

    dim3 grid(BATCH / (THREADS * CPT), BLOCKS);   // (16, 64) = 1024 CTAs

    // Module 0: normal launch (waits on alive prep via stream order).
    module_kernel<1><<<grid, THREADS>>>(biases, indices, angles, 0,
                                        input, scales, nullptr);

    // Modules 1..7: PDL — overlap launch/prologue (incl. sincos) with the
    // previous module's tail.
    for (int m = 1; m < DEPTH; m++) {
        const float* bia = biases + (size_t)m * 512;
        const int*   ix  = indices + (size_t)m * 1024;
        const float* ang = angles + (size_t)m * 4096;

        cudaLaunchConfig_t cfg = {};
        cfg.gridDim  = grid;
        cfg.blockDim = dim3(THREADS, 1, 1);
        cfg.dynamicSmemBytes = 0;
        cfg.stream = 0;
        cudaLaunchAttribute at[1];
        at[0].id = cudaLaunchAttributeProgrammaticStreamSerialization;
        at[0].val.programmaticStreamSerializationAllowed = 1;
        cfg.attrs = at;
        cfg.numAttrs = 1;

        if (m < DEPTH - 1)
            cudaLaunchKernelEx(&cfg, module_kernel<0>, bia, ix, ang, m,
                               (const float*)nullptr, (const float*)nullptr,
                               (float*)nullptr);
        else
            cudaLaunchKernelEx(&cfg, module_kernel<2>, bia, ix, ang, m,
                               (const float*)nullptr, (const float*)nullptr,
                               out);
    }
}

// round 13
// speedup vs baseline: 1.0278x; 1.0278x over previous
#include <cuda_runtime.h>

#define BATCH   4096
#define IN_W    1024
#define DEPTH   8
#define BLOCKS  64
#define NACT    8
#define GROW    512
#define TOTAL   5120
#define OUT_W   512

// 84 MB scratch state (static __device__ global: allowed, no runtime alloc)
__device__ float g_data[(size_t)TOTAL * BATCH];

typedef unsigned long long ull;

// Liveness masks: alive_sc[m][i] = row idx[m][i] is read by a later module;
// alive_act[m][u] = act row IN_W+512m+u is read by a later module. (m = 0..6)
__device__ unsigned char g_alive_sc[DEPTH - 1][1024];
__device__ unsigned char g_alive_act[DEPTH - 1][512];

__device__ __forceinline__ ull pk2(float x, float y) {
    ull r; asm("mov.b64 %0, {%1, %2};" : "=l"(r) : "f"(x), "f"(y)); return r;
}
__device__ __forceinline__ void upk2(ull v, float& x, float& y) {
    asm("mov.b64 {%0, %1}, %2;" : "=f"(x), "=f"(y) : "l"(v));
}
// Packed f32x2 FMA/MUL — Blackwell FFMA2 path (PTX-only)
__device__ __forceinline__ ull fma2(ull a, ull b, ull c) {
    ull d; asm("fma.rn.f32x2 %0, %1, %2, %3;" : "=l"(d) : "l"(a), "l"(b), "l"(c)); return d;
}
__device__ __forceinline__ ull mul2(ull a, ull b) {
    ull d; asm("mul.rn.f32x2 %0, %1, %2;" : "=l"(d) : "l"(a), "l"(b)); return d;
}
__device__ __forceinline__ float sqrt_ap(float x) {
    float r; asm("sqrt.approx.f32 %0, %1;" : "=f"(r) : "f"(x)); return r;
}
__device__ __forceinline__ float actf(float p) {
    return 0.5f * (p + sqrt_ap(fmaf(p, p, 1.0f)));
}
__device__ __forceinline__ ull mk_keep() {     // evict_last: row re-read later
    ull pol;
    asm("createpolicy.fractional.L2::evict_last.b64 %0, 1.0;" : "=l"(pol));
    return pol;
}
__device__ __forceinline__ ull mk_stream() {   // evict_first: last use
    ull pol;
    asm("createpolicy.fractional.L2::evict_first.b64 %0, 1.0;" : "=l"(pol));
    return pol;
}
__device__ __forceinline__ ull ldg_pol(const float* p, ull pol) {
    ull v;
    asm("ld.global.L2::cache_hint.b64 %0, [%1], %2;"
        : "=l"(v) : "l"(p), "l"(pol));
    return v;
}
__device__ __forceinline__ void stg_pol(float* p, ull v, ull pol) {
    asm volatile("st.global.L2::cache_hint.b64 [%0], %1, %2;"
                 :: "l"(p), "l"(v), "l"(pol));
}
__device__ __forceinline__ void stg_cs(float* p, ull v) {
    asm volatile("st.global.cs.b64 [%0], %1;" :: "l"(p), "l"(v));
}

// ---------------------------------------------------------------------------
// One-time: liveness masks via reverse sweep over indices.
// mark[r]=1 iff row r is read by a module > m.
// ---------------------------------------------------------------------------
__global__ void alive_kernel(const int* __restrict__ indices) {
    __shared__ unsigned char mark[TOTAL];
    const int t = threadIdx.x;
    #pragma unroll
    for (int i = t; i < TOTAL; i += 1024) mark[i] = 0;
    __syncthreads();
    mark[indices[7 * 1024 + t]] = 1;          // reads of the last module
    __syncthreads();
    for (int m = DEPTH - 2; m >= 0; m--) {
        g_alive_sc[m][t] = mark[indices[m * 1024 + t]];
        if (t < 512) g_alive_act[m][t] = mark[IN_W + GROW * m + t];
        __syncthreads();
        if (m > 0) {
            mark[indices[m * 1024 + t]] = 1;
            __syncthreads();
        }
    }
}

// ---------------------------------------------------------------------------
// One butterfly module. CUDA block = (butterfly blk) x (256 batch cols).
// Thread owns 2 batch columns of all 16 rows as f32x2; transform in registers.
// occ-7 cap (72 regs) -> all 1024 CTAs resident in ONE wave, 28 warps/SM.
// PDL prologue computes trig via sincosf (overlapped with previous module's
// tail); g_data touched only after griddepsync.
// MODE: 0 = middle, 1 = first (input*scales), 2 = last (act -> d_out)
// ---------------------------------------------------------------------------
template<int MODE>
__global__ __launch_bounds__(128, 7)
void module_kernel(const float* __restrict__ biases,  // [512]    this module
                   const int*   __restrict__ idx,     // [1024]   this module
                   const float* __restrict__ angles,  // [8][512] this module
                   int mod,
                   const float* __restrict__ input,   // (1024,4096) for FIRST
                   const float* __restrict__ scales,  // (1024,)     for FIRST
                   float* __restrict__ out_ext)       // d_out for LAST
{
    const int blk = blockIdx.y;
    const int tid = threadIdx.x;

    __shared__ int   s_idx[16];
    __shared__ ull   s_scl[16];
    __shared__ float s_bias[NACT];
    __shared__ unsigned char s_alsc[16];
    __shared__ unsigned char s_alact[NACT];
    __shared__ __align__(16) ulonglong2 s_cs[64];

    // ---- PDL prologue: tables + trig only, no g_data ----
    if (tid < 64) {
        int L = tid >> 3, a = tid & 7;
        float sn, cs;
        sincosf(angles[L * 512 + blk * 8 + a], &sn, &cs);
        s_cs[tid] = make_ulonglong2(pk2(cs, cs), pk2(sn, sn));
    }
    if (tid < 16) {
        int row = idx[blk * 16 + tid];
        s_idx[tid]  = row;
        s_alsc[tid] = (MODE == 2) ? 0 : g_alive_sc[mod][blk * 16 + tid];
        if (MODE == 1) { float s = scales[row]; s_scl[tid] = pk2(s, s); }
    }
    if (tid < 8) {
        s_bias[tid]  = biases[blk * 8 + tid];
        s_alact[tid] = (MODE == 2) ? 1 : g_alive_act[mod][blk * NACT + tid];
    }
    __syncthreads();

    const int b = (blockIdx.x * 128 + tid) * 2;   // first of 2 batch cols
    const ull SGN = 0x8000000080000000ULL;
    const ull pk  = mk_keep();
    const ull ps  = mk_stream();

    // ---- wait for previous module's stores ----
    if (MODE != 1) cudaGridDependencySynchronize();

    // Gather 16 rows (16 independent LDG.64 -> MLP=16). Last-use rows get
    // evict_first (they are also never scattered back).
    ull v[16];
    #pragma unroll
    for (int j = 0; j < 16; j++) {
        if (MODE == 1)
            v[j] = *(const ull*)(input + (size_t)s_idx[j] * BATCH + b);
        else
            v[j] = ldg_pol(g_data + (size_t)s_idx[j] * BATCH + b,
                           s_alsc[j] ? pk : ps);
    }
    if (MODE == 1) {
        #pragma unroll
        for (int j = 0; j < 16; j++) v[j] = mul2(v[j], s_scl[j]);
    }

    // 4 IN rotation layers (strides 1,2,4,8), all in registers
    #pragma unroll
    for (int k = 0; k < 4; k++) {
        const int st = 1 << k;
        #pragma unroll
        for (int g = 0; g < 16; g += 2 * st) {
            #pragma unroll
            for (int j = 0; j < st; j++) {
                const int lo = g + j, hi = lo + st;
                const ulonglong2 cs = s_cs[k * 8 + (g >> 1) + j];  // LDS.128
                const ull ns = cs.y ^ SGN;                         // -s on ALU
                ull xl = v[lo], xh = v[hi];
                v[lo] = fma2(cs.x, xl, mul2(cs.y, xh));
                v[hi] = fma2(ns,   xl, mul2(cs.x, xh));
            }
        }
    }

    // Activation on rows 0..7; write live act rows (d_out for last module)
    #pragma unroll
    for (int u = 0; u < NACT; u++) {
        const float bb = s_bias[u];
        float x0, x1;
        upk2(v[u], x0, x1);
        x0 = actf(x0 + bb); x1 = actf(x1 + bb);
        v[u] = pk2(x0, x1);
        if (MODE == 2)
            stg_cs(out_ext + (size_t)(blk * NACT + u) * BATCH + b, v[u]);
        else if (s_alact[u])
            stg_pol(g_data + (size_t)(IN_W + GROW * mod + blk * NACT + u) * BATCH + b,
                    v[u], pk);
    }

    if (MODE != 2) {
        // 4 OUT rotation layers (trig layers 4..7, strides 1,2,4,8)
        #pragma unroll
        for (int k = 0; k < 4; k++) {
            const int st = 1 << k;
            #pragma unroll
            for (int g = 0; g < 16; g += 2 * st) {
                #pragma unroll
                for (int j = 0; j < st; j++) {
                    const int lo = g + j, hi = lo + st;
                    const ulonglong2 cs = s_cs[(4 + k) * 8 + (g >> 1) + j];
                    const ull ns = cs.y ^ SGN;
                    ull xl = v[lo], xh = v[hi];
                    v[lo] = fma2(cs.x, xl, mul2(cs.y, xh));
                    v[hi] = fma2(ns,   xl, mul2(cs.x, xh));
                }
            }
        }
        // Scatter back only live rows (warp-uniform predicate)
        #pragma unroll
        for (int j = 0; j < 16; j++)
            if (s_alsc[j])
                stg_pol(g_data + (size_t)s_idx[j] * BATCH + b, v[j], pk);
    }

    // Let the next PDL kernel in as soon as our work is done.
    cudaTriggerProgrammaticLaunchCompletion();
}

// ---------------------------------------------------------------------------
extern "C" void kernel_launch(void* const* d_in, const int* in_sizes, int n_in,
                              void* d_out, int out_size) {
    const float* input   = (const float*)d_in[0];   // (1024, 4096)
    const float* scales  = (const float*)d_in[1];   // (1024,)
    const float* angles  = (const float*)d_in[2];   // (8, 8, 512)
    const float* biases  = (const float*)d_in[3];   // (8, 512)
    const int*   indices = (const int*)d_in[4];     // (8, 1024)
    float* out = (float*)d_out;                     // (512, 4096)

    alive_kernel<<<1, 1024>>>(indices);

    dim3 grid(BATCH / (128 * 2), BLOCKS);   // (16, 64) = 1024 CTAs, one wave

    // Module 0: normal launch (waits on alive prep via stream order).
    module_kernel<1><<<grid, 128>>>(biases, indices, angles, 0,
                                    input, scales, nullptr);

    // Modules 1..7: PDL — overlap launch/prologue (incl. sincos) with the
    // previous module's tail.
    for (int m = 1; m < DEPTH; m++) {
        const float* bia = biases + (size_t)m * 512;
        const int*   ix  = indices + (size_t)m * 1024;
        const float* ang = angles + (size_t)m * 4096;

        cudaLaunchConfig_t cfg = {};
        cfg.gridDim  = grid;
        cfg.blockDim = dim3(128, 1, 1);
        cfg.dynamicSmemBytes = 0;
        cfg.stream = 0;
        cudaLaunchAttribute at[1];
        at[0].id = cudaLaunchAttributeProgrammaticStreamSerialization;
        at[0].val.programmaticStreamSerializationAllowed = 1;
        cfg.attrs = at;
        cfg.numAttrs = 1;

        if (m < DEPTH - 1)
            cudaLaunchKernelEx(&cfg, module_kernel<0>, bia, ix, ang, m,
                               (const float*)nullptr, (const float*)nullptr,
                               (float*)nullptr);
        else
            cudaLaunchKernelEx(&cfg, module_kernel<2>, bia, ix, ang, m,
                               (const float*)nullptr, (const float*)nullptr,
                               out);
    }
}